// round 14
// baseline (speedup 1.0000x reference)
#include <cuda_runtime.h>
#include <cuda_fp16.h>
#include <math.h>
#include <stdint.h>

// ---------------- problem constants ----------------
#define B_      64
#define EVI_    5
#define SEQS_   (B_ * EVI_)          // 320
#define L_      256
#define D_      768
#define D2_     (D_ / 2)             // 384 u32 per fp16-pair row
#define WORDS_  32
#define TPW_    4
#define NN_     (SEQS_ * WORDS_)     // 10240 nodes
#define EE_     (NN_ * 16)           // 163840 edges
#define R_      4
#define DOUT_   768
#define LH_     1024
#define NC_     3
#define KTOT_   (5 * D_)             // 3840 fused K
#define NR_     (NN_ * R_)           // 40960 segments
#define KP2_    (KTOT_ / 2)          // 1920 k-pairs

// ---------------- scratch (device globals; no allocs allowed) ----------------
__device__ uint32_t g_hh  [(size_t)R_ * NN_ * D2_];  // fp16 h, k-pair packed
__device__ uint32_t g_xh  [(size_t)NN_ * D2_];       // fp16 x0
__device__ uint32_t g_yh  [(size_t)NN_ * D2_];       // fp16 x1
__device__ uint32_t g_bh1 [(size_t)KP2_ * D_];       // fp16 Wcat layer 1
__device__ uint32_t g_bh2 [(size_t)KP2_ * D_];       // fp16 Wcat layer 2
__device__ int      g_cnt [NR_];
__device__ int      g_off [NR_ + 1];
__device__ int      g_cur [NR_];
__device__ int      g_elist[EE_];
__device__ float    g_ev  [SEQS_ * 2 * DOUT_];
__device__ float    g_cc  [B_ * D_];                 // claim cls rows
__device__ float    g_hcc [B_ * DOUT_];              // cc @ W_top
__device__ float    g_hatt[SEQS_ * DOUT_];           // ev @ W_bot
__device__ float    g_a   [SEQS_];
__device__ float    g_rep [B_ * (2 * DOUT_ + D_)];
__device__ float    g_hid [B_ * LH_];

// ---------------- small device helpers ----------------
__device__ __forceinline__ uint32_t smem_u32(const void* p) {
    uint32_t a;
    asm("{ .reg .u64 t; cvta.to.shared.u64 t, %1; cvt.u32.u64 %0, t; }" : "=r"(a) : "l"(p));
    return a;
}
__device__ __forceinline__ uint32_t packh2(float v0, float v1) {
    __half h0 = __float2half_rn(v0);
    __half h1 = __float2half_rn(v1);
    return ((uint32_t)__half_as_ushort(h1) << 16) | (uint32_t)__half_as_ushort(h0);
}
__device__ __forceinline__ float2 unpackh2(uint32_t u) {
    __half2 h = *(__half2*)&u;
    return __half22float2(h);
}
__device__ __forceinline__ void mma16816h(float* c, const uint32_t* a, const uint32_t* b) {
    asm volatile("mma.sync.aligned.m16n8k16.row.col.f32.f16.f16.f32 "
                 "{%0,%1,%2,%3}, {%4,%5,%6,%7}, {%8,%9}, {%0,%1,%2,%3};"
                 : "+f"(c[0]), "+f"(c[1]), "+f"(c[2]), "+f"(c[3])
                 : "r"(a[0]), "r"(a[1]), "r"(a[2]), "r"(a[3]), "r"(b[0]), "r"(b[1]));
}
__device__ __forceinline__ void cp16(uint32_t dst, const void* src) {
    asm volatile("cp.async.cg.shared.global [%0], [%1], 16;" :: "r"(dst), "l"(src));
}
__device__ __forceinline__ void red4(float* p, float a, float b, float c, float d) {
    asm volatile("red.global.add.v4.f32 [%0], {%1,%2,%3,%4};"
                 :: "l"(p), "f"(a), "f"(b), "f"(c), "f"(d) : "memory");
}

// ---------------- mega prep kernel ----------------
// zero cnt | gather_mean x0 | convertB both | zero hatt | zero hcc | gather cc
#define PR0 ((long long)NN_ * D2_)              // gather_mean
#define PR1 ((long long)KP2_ * D_)              // convertB
#define PR2 ((long long)NR_)                    // zero cnt
#define PR3 ((long long)SEQS_ * DOUT_)          // zero hatt
#define PR4 ((long long)B_ * DOUT_)             // zero hcc
#define PR5 ((long long)B_ * D_)                // gather cc
#define PRTOT (PR0 + PR1 + PR2 + PR3 + PR4 + PR5)

__global__ void prep_kernel(const float* __restrict__ tok, const int* __restrict__ wti,
                            const float* __restrict__ Wrel1, const float* __restrict__ Wroot1,
                            const float* __restrict__ Wrel2, const float* __restrict__ Wroot2,
                            const int* __restrict__ csi) {
    long long t = (long long)blockIdx.x * blockDim.x + threadIdx.x;
    if (t < PR0) {
        int n = (int)(t / D2_);
        int d = (int)(t % D2_) * 2;
        const int* w = wti + n * TPW_;
        float v0 = 0.f, v1 = 0.f;
#pragma unroll
        for (int i = 0; i < TPW_; ++i) {
            const float* r = tok + (size_t)w[i] * D_ + d;
            v0 += r[0]; v1 += r[1];
        }
        g_xh[t] = packh2(v0 * 0.25f, v1 * 0.25f);
        return;
    }
    t -= PR0;
    if (t < PR1) {
        int k2 = (int)(t / D_);
        int n  = (int)(t - (long long)k2 * D_);
        int k  = 2 * k2;
        if (k < 4 * D_) {
            const float* b1 = Wrel1 + (size_t)k * D_ + n;
            const float* b2 = Wrel2 + (size_t)k * D_ + n;
            g_bh1[t] = packh2(b1[0], b1[D_]);
            g_bh2[t] = packh2(b2[0], b2[D_]);
        } else {
            const float* b1 = Wroot1 + (size_t)(k - 4 * D_) * D_ + n;
            const float* b2 = Wroot2 + (size_t)(k - 4 * D_) * D_ + n;
            g_bh1[t] = packh2(b1[0], b1[D_]);
            g_bh2[t] = packh2(b2[0], b2[D_]);
        }
        return;
    }
    t -= PR1;
    if (t < PR2) { g_cnt[t] = 0; return; }
    t -= PR2;
    if (t < PR3) { g_hatt[t] = 0.f; return; }
    t -= PR3;
    if (t < PR4) { g_hcc[t] = 0.f; return; }
    t -= PR4;
    if (t < PR5) {
        int b = (int)(t / D_), c = (int)(t % D_);
        g_cc[t] = tok[(size_t)csi[b] * L_ * D_ + c];
    }
}

// ---------------- graph prep: counts -> scan -> scatter (CSR) ----------------
__global__ void count_kernel(const int* __restrict__ eidx, const int* __restrict__ etype) {
    int e = blockIdx.x * blockDim.x + threadIdx.x;
    if (e >= EE_) return;
    atomicAdd(&g_cnt[eidx[EE_ + e] * R_ + etype[e]], 1);
}
__global__ void scan_kernel() {
    __shared__ int part[1024];
    int tid = threadIdx.x;
    int base = tid * 40;
    int s = 0;
#pragma unroll 8
    for (int i = 0; i < 40; ++i) s += g_cnt[base + i];
    part[tid] = s;
    __syncthreads();
    for (int o = 1; o < 1024; o <<= 1) {
        int v = (tid >= o) ? part[tid - o] : 0;
        __syncthreads();
        part[tid] += v;
        __syncthreads();
    }
    int run = tid ? part[tid - 1] : 0;
#pragma unroll 8
    for (int i = 0; i < 40; ++i) {
        int c = g_cnt[base + i];
        g_off[base + i] = run;
        g_cur[base + i] = run;
        run += c;
    }
    if (tid == 1023) g_off[NR_] = run;
}
__global__ void scatter_kernel(const int* __restrict__ eidx, const int* __restrict__ etype) {
    int e = blockIdx.x * blockDim.x + threadIdx.x;
    if (e >= EE_) return;
    int pos = atomicAdd(&g_cur[eidx[EE_ + e] * R_ + etype[e]], 1);
    g_elist[pos] = eidx[e];
}

// grid (NN_, R_): one CTA per (dst, relation); 192 threads, 2 u32 each; 4-wide unroll.
__global__ void __launch_bounds__(192)
csr_agg_kernel(const uint32_t* __restrict__ xh) {
    int dst = blockIdx.x;
    int r   = blockIdx.y;
    int q = threadIdx.x * 2;
    int beg = g_off[dst * R_ + r];
    int end = g_off[dst * R_ + r + 1];
    float4 a = make_float4(0.f, 0.f, 0.f, 0.f);
    int i = beg;
    for (; i + 4 <= end; i += 4) {
        int s0 = g_elist[i], s1 = g_elist[i + 1], s2 = g_elist[i + 2], s3 = g_elist[i + 3];
        uint2 v0 = *(const uint2*)(xh + (size_t)s0 * D2_ + q);
        uint2 v1 = *(const uint2*)(xh + (size_t)s1 * D2_ + q);
        uint2 v2 = *(const uint2*)(xh + (size_t)s2 * D2_ + q);
        uint2 v3 = *(const uint2*)(xh + (size_t)s3 * D2_ + q);
        float2 f;
        f = unpackh2(v0.x); a.x += f.x; a.y += f.y;
        f = unpackh2(v0.y); a.z += f.x; a.w += f.y;
        f = unpackh2(v1.x); a.x += f.x; a.y += f.y;
        f = unpackh2(v1.y); a.z += f.x; a.w += f.y;
        f = unpackh2(v2.x); a.x += f.x; a.y += f.y;
        f = unpackh2(v2.y); a.z += f.x; a.w += f.y;
        f = unpackh2(v3.x); a.x += f.x; a.y += f.y;
        f = unpackh2(v3.y); a.z += f.x; a.w += f.y;
    }
    for (; i < end; ++i) {
        int src = g_elist[i];
        uint2 v = *(const uint2*)(xh + (size_t)src * D2_ + q);
        float2 f0 = unpackh2(v.x);
        float2 f1 = unpackh2(v.y);
        a.x += f0.x; a.y += f0.y; a.z += f1.x; a.w += f1.y;
    }
    float s = (end > beg) ? (1.f / (float)(end - beg)) : 0.f;
    size_t o = ((size_t)r * NN_ + dst) * D2_ + q;
    *(uint2*)&g_hh[o] = make_uint2(packh2(a.x * s, a.y * s), packh2(a.z * s, a.w * s));
}

// ---------------- fp16 single-pass tensor GEMM: 4-stage cp.async ring ----------------
// relu( [h0|h1|h2|h3|x] @ Wcat + bias ) -> fp16 Yh, or pooled mean|max -> Ev
#define GBM 128
#define GBN 256
#define GBK 32
#define NSTG (KTOT_ / GBK)   // 120
#define AP_  20
#define BP_  264
#define ASZ_ (GBM * AP_)     // 2560 u32
#define BSZ_ (16 * BP_)      // 4224 u32
#define SBUF (ASZ_ + BSZ_)   // 6784 u32 per stage
#define GSMEM (4 * SBUF * 4) // 108544 bytes

__global__ void __launch_bounds__(256, 1)
gemm_rgcn(const uint32_t* __restrict__ Hh, const uint32_t* __restrict__ Xh,
          const uint32_t* __restrict__ Bh,
          const float* __restrict__ bias,
          uint32_t* __restrict__ Yh, float* __restrict__ Ev) {
    extern __shared__ uint32_t sm[];
    const uint32_t sb = smem_u32(sm);
    const int tid  = threadIdx.x;
    const int wid  = tid >> 5;
    const int lane = tid & 31;
    const int g    = lane >> 2;
    const int tc   = lane & 3;
    const int wm   = wid & 3;        // 0..3 -> 32-row slice (one sequence)
    const int wn   = wid >> 2;       // 0..1 -> 128-col slice
    const int m0   = blockIdx.y * GBM;
    const int n0   = blockIdx.x * GBN;

    float acc[2][16][4];
#pragma unroll
    for (int i = 0; i < 2; ++i)
#pragma unroll
        for (int j = 0; j < 16; ++j)
#pragma unroll
            for (int q = 0; q < 4; ++q) acc[i][j][q] = 0.f;

    auto issueA = [&](int kc, int buf) {
        const int k0 = kc * GBK;
        const int r  = k0 / D_;
        const int dq = (k0 - r * D_) >> 1;
        const uint32_t* src = (r < 4) ? (Hh + ((size_t)r * NN_ + m0) * D2_ + dq)
                                      : (Xh + (size_t)m0 * D2_ + dq);
        const uint32_t aB = sb + (uint32_t)buf * (SBUF * 4);
#pragma unroll
        for (int i = 0; i < 2; ++i) {
            int c = tid + i * 256;
            int row = c >> 2, seg = c & 3;
            cp16(aB + row * (AP_ * 4) + seg * 16, src + (size_t)row * D2_ + seg * 4);
        }
    };
    auto issueB = [&](int kc, int buf) {
        const int kp0 = kc * 16;
        const uint32_t bbH = sb + (uint32_t)buf * (SBUF * 4) + ASZ_ * 4;
#pragma unroll
        for (int i = 0; i < 4; ++i) {
            int c = tid + i * 256;
            int row = c >> 6, seg = c & 63;
            size_t gidx = (size_t)(kp0 + row) * D_ + n0 + seg * 4;
            cp16(bbH + row * (BP_ * 4) + seg * 16, Bh + gidx);
        }
    };
    auto compute = [&](const uint32_t* s) {
        const uint32_t* AsH = s;
        const uint32_t* BsH = s + ASZ_;
#pragma unroll
        for (int ks = 0; ks < 2; ++ks) {
            const int kb = ks * 8;
            uint32_t aH[2][4];
#pragma unroll
            for (int mt = 0; mt < 2; ++mt) {
                int i0 = (wm * 32 + mt * 16 + g) * AP_ + kb + tc;
                int i1 = i0 + 8 * AP_;
                aH[mt][0] = AsH[i0]; aH[mt][1] = AsH[i1];
                aH[mt][2] = AsH[i0 + 4]; aH[mt][3] = AsH[i1 + 4];
            }
#pragma unroll
            for (int ng = 0; ng < 4; ++ng) {
                uint32_t bh[4][2];
#pragma unroll
                for (int q = 0; q < 4; ++q) {
                    int cb = wn * 128 + (ng * 4 + q) * 8;
                    int j0 = (kb + tc) * BP_ + cb + g;
                    int j1 = j0 + 4 * BP_;
                    bh[q][0] = BsH[j0]; bh[q][1] = BsH[j1];
                }
#pragma unroll
                for (int mt = 0; mt < 2; ++mt)
#pragma unroll
                    for (int q = 0; q < 4; ++q)
                        mma16816h(acc[mt][ng * 4 + q], aH[mt], bh[q]);
            }
        }
    };

    issueA(0, 0); issueB(0, 0);
    asm volatile("cp.async.commit_group;" ::: "memory");
    issueA(1, 1); issueB(1, 1);
    asm volatile("cp.async.commit_group;" ::: "memory");

#pragma unroll 1
    for (int kc = 0; kc < NSTG; ++kc) {
        if (kc + 2 < NSTG) {
            int buf = (kc + 2) & 3;
            issueA(kc + 2, buf);
            issueB(kc + 2, buf);
            asm volatile("cp.async.commit_group;" ::: "memory");
            asm volatile("cp.async.wait_group 2;" ::: "memory");
        } else if (kc + 1 < NSTG) {
            asm volatile("cp.async.wait_group 1;" ::: "memory");
        } else {
            asm volatile("cp.async.wait_group 0;" ::: "memory");
        }
        __syncthreads();
        compute(sm + (uint32_t)(kc & 3) * SBUF);
    }

    if (Ev) {
        // ---- pooled epilogue: bias+relu, mean/max over the 32 words (this warp's rows) ----
        const int seq = blockIdx.y * 4 + wm;
#pragma unroll
        for (int nt = 0; nt < 16; ++nt) {
            int col = n0 + wn * 128 + nt * 8 + tc * 2;
            float b0 = __ldg(bias + col);
            float b1 = __ldg(bias + col + 1);
            float s0 = 0.f, s1 = 0.f, x0 = 0.f, x1 = 0.f;
#pragma unroll
            for (int mt = 0; mt < 2; ++mt) {
                float v;
                v = fmaxf(acc[mt][nt][0] + b0, 0.f); s0 += v; x0 = fmaxf(x0, v);
                v = fmaxf(acc[mt][nt][2] + b0, 0.f); s0 += v; x0 = fmaxf(x0, v);
                v = fmaxf(acc[mt][nt][1] + b1, 0.f); s1 += v; x1 = fmaxf(x1, v);
                v = fmaxf(acc[mt][nt][3] + b1, 0.f); s1 += v; x1 = fmaxf(x1, v);
            }
#pragma unroll
            for (int off = 4; off <= 16; off <<= 1) {
                s0 += __shfl_xor_sync(0xffffffffu, s0, off);
                s1 += __shfl_xor_sync(0xffffffffu, s1, off);
                x0 = fmaxf(x0, __shfl_xor_sync(0xffffffffu, x0, off));
                x1 = fmaxf(x1, __shfl_xor_sync(0xffffffffu, x1, off));
            }
            if (lane < 4) {
                float* evr = Ev + (size_t)seq * (2 * DOUT_);
                evr[col]             = s0 * (1.f / WORDS_);
                evr[col + 1]         = s1 * (1.f / WORDS_);
                evr[DOUT_ + col]     = x0;
                evr[DOUT_ + col + 1] = x1;
            }
        }
    } else {
        // ---- standard epilogue: bias + relu -> fp16 ----
#pragma unroll
        for (int mt = 0; mt < 2; ++mt) {
            int row = m0 + wm * 32 + mt * 16 + g;
#pragma unroll
            for (int nt = 0; nt < 16; ++nt) {
                int col = n0 + wn * 128 + nt * 8 + tc * 2;
                float b0 = __ldg(bias + col);
                float b1 = __ldg(bias + col + 1);
                float2 v0 = make_float2(fmaxf(acc[mt][nt][0] + b0, 0.f),
                                        fmaxf(acc[mt][nt][1] + b1, 0.f));
                float2 v1 = make_float2(fmaxf(acc[mt][nt][2] + b0, 0.f),
                                        fmaxf(acc[mt][nt][3] + b1, 0.f));
                Yh[(size_t)row * D2_ + (col >> 1)]       = packh2(v0.x, v0.y);
                Yh[(size_t)(row + 8) * D2_ + (col >> 1)] = packh2(v1.x, v1.y);
            }
        }
    }
}

// ---------------- split-K fp32 GEMM for head ops ----------------
#define HB 64
#define HK 16
__global__ void __launch_bounds__(256)
sgemm_splitk(const float* __restrict__ A, const float* __restrict__ Bm,
             float* __restrict__ C, int M, int N, int K, int kchunk) {
    __shared__ float As[HK][HB + 4];
    __shared__ float Bs[HK][HB + 4];
    const int tid = threadIdx.x;
    const int tr = tid >> 4;
    const int tcol = tid & 15;
    const int m0 = blockIdx.y * HB;
    const int n0 = blockIdx.x * HB;
    const int k0 = blockIdx.z * kchunk;
    const int ar = tid >> 2, ac = (tid & 3) * 4;
    const int br = tid >> 4, bc = (tid & 15) * 4;
    float acc[4][4] = {};
    for (int kk = 0; kk < kchunk; kk += HK) {
        int k = k0 + kk;
        float4 av = (m0 + ar < M) ? *(const float4*)(A + (size_t)(m0 + ar) * K + k + ac)
                                  : make_float4(0.f, 0.f, 0.f, 0.f);
        As[ac + 0][ar] = av.x;
        As[ac + 1][ar] = av.y;
        As[ac + 2][ar] = av.z;
        As[ac + 3][ar] = av.w;
        *(float4*)&Bs[br][bc] = *(const float4*)(Bm + (size_t)(k + br) * N + n0 + bc);
        __syncthreads();
#pragma unroll
        for (int kq = 0; kq < HK; ++kq) {
            float rm[4], rn[4];
#pragma unroll
            for (int i = 0; i < 4; ++i) rm[i] = As[kq][tr * 4 + i];
#pragma unroll
            for (int j = 0; j < 4; ++j) rn[j] = Bs[kq][tcol * 4 + j];
#pragma unroll
            for (int i = 0; i < 4; ++i)
#pragma unroll
                for (int j = 0; j < 4; ++j)
                    acc[i][j] += rm[i] * rn[j];
        }
        __syncthreads();
    }
#pragma unroll
    for (int i = 0; i < 4; ++i) {
        int row = m0 + tr * 4 + i;
        if (row < M)
            red4(C + (size_t)row * N + n0 + tcol * 4,
                 acc[i][0], acc[i][1], acc[i][2], acc[i][3]);
    }
}

// ---------------- fused head kernels ----------------
// p[s] = sum_k relu(hcc[b][k] + hatt[s][k]) * w1[k]; softmax over EVI; sigmoid out
__global__ void dotp_softmax_kernel(const float* __restrict__ att_w1, float* __restrict__ out) {
    int b = blockIdx.x;
    int tid = threadIdx.x;
    __shared__ float red[8];
    __shared__ float pv[EVI_];
#pragma unroll
    for (int e = 0; e < EVI_; ++e) {
        int s = b * EVI_ + e;
        float acc = 0.f;
        for (int k = tid; k < DOUT_; k += 256) {
            float h = g_hcc[b * DOUT_ + k] + g_hatt[(size_t)s * DOUT_ + k];
            acc += fmaxf(h, 0.f) * att_w1[k];
        }
#pragma unroll
        for (int o = 16; o; o >>= 1) acc += __shfl_down_sync(0xffffffffu, acc, o);
        if ((tid & 31) == 0) red[tid >> 5] = acc;
        __syncthreads();
        if (tid == 0) {
            float r = 0.f;
#pragma unroll
            for (int w = 0; w < 8; ++w) r += red[w];
            pv[e] = r;
        }
        __syncthreads();
    }
    if (tid == 0) {
        float m = -1e30f;
#pragma unroll
        for (int e = 0; e < EVI_; ++e) m = fmaxf(m, pv[e]);
        float s = 0.f;
        float ex[EVI_];
#pragma unroll
        for (int e = 0; e < EVI_; ++e) { ex[e] = expf(pv[e] - m); s += ex[e]; }
        float is = 1.f / s;
#pragma unroll
        for (int e = 0; e < EVI_; ++e) {
            g_a[b * EVI_ + e] = ex[e] * is;
            out[B_ * NC_ + b * EVI_ + e] = 1.f / (1.f + expf(-pv[e]));
        }
    }
}
__global__ void rep_bias_kernel(const float* __restrict__ concat_cls, const float* __restrict__ lin1_b) {
    int t = blockIdx.x * blockDim.x + threadIdx.x;
    const int W = 2 * DOUT_ + D_;
    const int NR = B_ * W;
    if (t < NR) {
        int b = t / W, c = t % W;
        if (c < 2 * DOUT_) {
            float acc = 0.f;
#pragma unroll
            for (int e = 0; e < EVI_; ++e)
                acc += g_a[b * EVI_ + e] * g_ev[(size_t)(b * EVI_ + e) * (2 * DOUT_) + c];
            g_rep[t] = acc;
        } else {
            g_rep[t] = concat_cls[b * D_ + (c - 2 * DOUT_)];
        }
    } else {
        int u = t - NR;
        if (u < B_ * LH_) g_hid[u] = lin1_b[u % LH_];
    }
}
__global__ void final_kernel(const float* __restrict__ lin2_w,
                             const float* __restrict__ lin2_b,
                             float* __restrict__ out) {
    int b = blockIdx.x;
    int tid = threadIdx.x;
    float a0 = 0.f, a1 = 0.f, a2 = 0.f;
    for (int k = tid; k < LH_; k += 128) {
        float h = fmaxf(g_hid[(size_t)b * LH_ + k], 0.f);
        a0 += h * lin2_w[k * NC_ + 0];
        a1 += h * lin2_w[k * NC_ + 1];
        a2 += h * lin2_w[k * NC_ + 2];
    }
#pragma unroll
    for (int o = 16; o; o >>= 1) {
        a0 += __shfl_down_sync(0xffffffffu, a0, o);
        a1 += __shfl_down_sync(0xffffffffu, a1, o);
        a2 += __shfl_down_sync(0xffffffffu, a2, o);
    }
    __shared__ float s0[4], s1[4], s2[4];
    if ((tid & 31) == 0) { int w = tid >> 5; s0[w] = a0; s1[w] = a1; s2[w] = a2; }
    __syncthreads();
    if (tid == 0) {
        float l0 = s0[0] + s0[1] + s0[2] + s0[3] + lin2_b[0];
        float l1 = s1[0] + s1[1] + s1[2] + s1[3] + lin2_b[1];
        float l2 = s2[0] + s2[1] + s2[2] + s2[3] + lin2_b[2];
        float m = fmaxf(l0, fmaxf(l1, l2));
        float lse = logf(expf(l0 - m) + expf(l1 - m) + expf(l2 - m)) + m;
        out[b * NC_ + 0] = l0 - lse;
        out[b * NC_ + 1] = l1 - lse;
        out[b * NC_ + 2] = l2 - lse;
    }
}

// ---------------- launch ----------------
extern "C" void kernel_launch(void* const* d_in, const int* in_sizes, int n_in,
                              void* d_out, int out_size) {
    const float* token_feats = (const float*)d_in[0];
    const float* concat_cls  = (const float*)d_in[1];
    const float* W_rel1      = (const float*)d_in[2];
    const float* W_root1     = (const float*)d_in[3];
    const float* b1          = (const float*)d_in[4];
    const float* W_rel2      = (const float*)d_in[5];
    const float* W_root2     = (const float*)d_in[6];
    const float* b2          = (const float*)d_in[7];
    const float* att_w0      = (const float*)d_in[8];
    const float* att_w1      = (const float*)d_in[9];
    const float* lin1_w      = (const float*)d_in[10];
    const float* lin1_b      = (const float*)d_in[11];
    const float* lin2_w      = (const float*)d_in[12];
    const float* lin2_b      = (const float*)d_in[13];
    const int*   wti         = (const int*)d_in[14];
    const int*   eidx        = (const int*)d_in[15];
    const int*   etype       = (const int*)d_in[16];
    const int*   csi         = (const int*)d_in[17];
    float* out = (float*)d_out;

    float *p_ev, *p_cc, *p_hcc, *p_hatt, *p_rep, *p_hid;
    uint32_t *p_hh, *p_xh, *p_yh, *p_bh1, *p_bh2;
    cudaGetSymbolAddress((void**)&p_ev,    g_ev);
    cudaGetSymbolAddress((void**)&p_cc,    g_cc);
    cudaGetSymbolAddress((void**)&p_hcc,   g_hcc);
    cudaGetSymbolAddress((void**)&p_hatt,  g_hatt);
    cudaGetSymbolAddress((void**)&p_rep,   g_rep);
    cudaGetSymbolAddress((void**)&p_hid,   g_hid);
    cudaGetSymbolAddress((void**)&p_hh,    g_hh);
    cudaGetSymbolAddress((void**)&p_xh,    g_xh);
    cudaGetSymbolAddress((void**)&p_yh,    g_yh);
    cudaGetSymbolAddress((void**)&p_bh1,   g_bh1);
    cudaGetSymbolAddress((void**)&p_bh2,   g_bh2);

    cudaFuncSetAttribute(gemm_rgcn, cudaFuncAttributeMaxDynamicSharedMemorySize, GSMEM);

    const int T = 256;
    const dim3 ggrid(D_ / GBN, NN_ / GBM);   // (3, 80)
    const dim3 agrid(NN_, R_);
    const int HKW = D_ + 2 * DOUT_;          // 2304

    // --- mega prep: zero cnt | x0 fp16 | both W fp16 | zero hatt/hcc | gather cc ---
    prep_kernel<<<(unsigned)((PRTOT + T - 1) / T), T>>>(token_feats, wti,
                                                        W_rel1, W_root1, W_rel2, W_root2, csi);

    // --- CSR build ---
    count_kernel<<<(EE_ + T - 1) / T, T>>>(eidx, etype);
    scan_kernel<<<1, 1024>>>();
    scatter_kernel<<<(EE_ + T - 1) / T, T>>>(eidx, etype);

    // --- hcc = cc @ W_top (independent of layers; overlaps launch stream slack) ---
    {
        dim3 hg(DOUT_ / HB, 1, 4);            // (12, 1, 4), kchunk=192
        sgemm_splitk<<<hg, 256>>>(p_cc, att_w0, p_hcc, B_, DOUT_, D_, D_ / 4);
    }

    // --- layer 1 (fp16 -> fp16) ---
    csr_agg_kernel<<<agrid, 192>>>(p_xh);
    gemm_rgcn<<<ggrid, 256, GSMEM>>>(p_hh, p_xh, p_bh1, b1, p_yh, nullptr);

    // --- layer 2 (fp16 -> pooled ev directly) ---
    csr_agg_kernel<<<agrid, 192>>>(p_yh);
    gemm_rgcn<<<ggrid, 256, GSMEM>>>(p_hh, p_yh, p_bh2, b2, nullptr, p_ev);

    // --- attention head: hatt = ev @ W_bot ---
    {
        dim3 hg(DOUT_ / HB, (SEQS_ + HB - 1) / HB, 6);   // (12, 5, 6), kchunk=256
        sgemm_splitk<<<hg, 256>>>(p_ev, att_w0 + (size_t)D_ * DOUT_, p_hatt,
                                  SEQS_, DOUT_, 2 * DOUT_, 2 * DOUT_ / 6);
    }
    dotp_softmax_kernel<<<B_, 256>>>(att_w1, out);

    // --- graph readout + classifier ---
    {
        int tot = B_ * HKW + B_ * LH_;
        rep_bias_kernel<<<(tot + T - 1) / T, T>>>(concat_cls, lin1_b);
    }
    {
        dim3 hg(LH_ / HB, (B_ + HB - 1) / HB, 8);        // (16, 1, 8), kchunk=288
        sgemm_splitk<<<hg, 256>>>(p_rep, lin1_w, p_hid, B_, LH_, HKW, HKW / 8);
    }
    final_kernel<<<B_, 128>>>(lin2_w, lin2_b, out);
}

// round 15
// speedup vs baseline: 1.0185x; 1.0185x over previous
#include <cuda_runtime.h>
#include <cuda_fp16.h>
#include <math.h>
#include <stdint.h>

// ---------------- problem constants ----------------
#define B_      64
#define EVI_    5
#define SEQS_   (B_ * EVI_)          // 320
#define L_      256
#define D_      768
#define D2_     (D_ / 2)             // 384 u32 per fp16-pair row
#define WORDS_  32
#define TPW_    4
#define NN_     (SEQS_ * WORDS_)     // 10240 nodes
#define EE_     (NN_ * 16)           // 163840 edges
#define R_      4
#define DOUT_   768
#define LH_     1024
#define NC_     3
#define KTOT_   (5 * D_)             // 3840 fused K
#define NR_     (NN_ * R_)           // 40960 segments
#define KP2_    (KTOT_ / 2)          // 1920 k-pairs

// ---------------- scratch (device globals; no allocs allowed) ----------------
__device__ uint32_t g_hh  [(size_t)R_ * NN_ * D2_];  // fp16 h, k-pair packed
__device__ uint32_t g_xh  [(size_t)NN_ * D2_];       // fp16 x0
__device__ uint32_t g_yh  [(size_t)NN_ * D2_];       // fp16 x1
__device__ uint32_t g_bh1 [(size_t)KP2_ * D_];       // fp16 Wcat layer 1
__device__ uint32_t g_bh2 [(size_t)KP2_ * D_];       // fp16 Wcat layer 2
__device__ int      g_cnt [NR_];
__device__ int      g_off [NR_ + 1];
__device__ int      g_cur [NR_];
__device__ int      g_elist[EE_];
__device__ float    g_ev  [SEQS_ * 2 * DOUT_];
__device__ float    g_cc  [B_ * D_];                 // claim cls rows
__device__ float    g_hcc [B_ * DOUT_];              // cc @ W_top
__device__ float    g_hatt[SEQS_ * DOUT_];           // ev @ W_bot
__device__ float    g_a   [SEQS_];
__device__ float    g_rep [B_ * (2 * DOUT_ + D_)];
__device__ float    g_hid [B_ * LH_];

// ---------------- small device helpers ----------------
__device__ __forceinline__ uint32_t smem_u32(const void* p) {
    uint32_t a;
    asm("{ .reg .u64 t; cvta.to.shared.u64 t, %1; cvt.u32.u64 %0, t; }" : "=r"(a) : "l"(p));
    return a;
}
__device__ __forceinline__ uint32_t packh2(float v0, float v1) {
    __half h0 = __float2half_rn(v0);
    __half h1 = __float2half_rn(v1);
    return ((uint32_t)__half_as_ushort(h1) << 16) | (uint32_t)__half_as_ushort(h0);
}
__device__ __forceinline__ float2 unpackh2(uint32_t u) {
    __half2 h = *(__half2*)&u;
    return __half22float2(h);
}
__device__ __forceinline__ void mma16816h(float* c, const uint32_t* a, const uint32_t* b) {
    asm volatile("mma.sync.aligned.m16n8k16.row.col.f32.f16.f16.f32 "
                 "{%0,%1,%2,%3}, {%4,%5,%6,%7}, {%8,%9}, {%0,%1,%2,%3};"
                 : "+f"(c[0]), "+f"(c[1]), "+f"(c[2]), "+f"(c[3])
                 : "r"(a[0]), "r"(a[1]), "r"(a[2]), "r"(a[3]), "r"(b[0]), "r"(b[1]));
}
__device__ __forceinline__ void cp16(uint32_t dst, const void* src) {
    asm volatile("cp.async.cg.shared.global [%0], [%1], 16;" :: "r"(dst), "l"(src));
}
__device__ __forceinline__ void red4(float* p, float a, float b, float c, float d) {
    asm volatile("red.global.add.v4.f32 [%0], {%1,%2,%3,%4};"
                 :: "l"(p), "f"(a), "f"(b), "f"(c), "f"(d) : "memory");
}

// ---------------- mega prep kernel ----------------
#define PR0 ((long long)NN_ * D2_)              // gather_mean
#define PR1 ((long long)KP2_ * D_)              // convertB
#define PR2 ((long long)NR_)                    // zero cnt
#define PR3 ((long long)SEQS_ * DOUT_)          // zero hatt
#define PR4 ((long long)B_ * DOUT_)             // zero hcc
#define PR5 ((long long)B_ * D_)                // gather cc
#define PRTOT (PR0 + PR1 + PR2 + PR3 + PR4 + PR5)

__global__ void prep_kernel(const float* __restrict__ tok, const int* __restrict__ wti,
                            const float* __restrict__ Wrel1, const float* __restrict__ Wroot1,
                            const float* __restrict__ Wrel2, const float* __restrict__ Wroot2,
                            const int* __restrict__ csi) {
    long long t = (long long)blockIdx.x * blockDim.x + threadIdx.x;
    if (t < PR0) {
        int n = (int)(t / D2_);
        int d = (int)(t % D2_) * 2;
        const int* w = wti + n * TPW_;
        float v0 = 0.f, v1 = 0.f;
#pragma unroll
        for (int i = 0; i < TPW_; ++i) {
            const float* r = tok + (size_t)w[i] * D_ + d;
            v0 += r[0]; v1 += r[1];
        }
        g_xh[t] = packh2(v0 * 0.25f, v1 * 0.25f);
        return;
    }
    t -= PR0;
    if (t < PR1) {
        int k2 = (int)(t / D_);
        int n  = (int)(t - (long long)k2 * D_);
        int k  = 2 * k2;
        if (k < 4 * D_) {
            const float* b1 = Wrel1 + (size_t)k * D_ + n;
            const float* b2 = Wrel2 + (size_t)k * D_ + n;
            g_bh1[t] = packh2(b1[0], b1[D_]);
            g_bh2[t] = packh2(b2[0], b2[D_]);
        } else {
            const float* b1 = Wroot1 + (size_t)(k - 4 * D_) * D_ + n;
            const float* b2 = Wroot2 + (size_t)(k - 4 * D_) * D_ + n;
            g_bh1[t] = packh2(b1[0], b1[D_]);
            g_bh2[t] = packh2(b2[0], b2[D_]);
        }
        return;
    }
    t -= PR1;
    if (t < PR2) { g_cnt[t] = 0; return; }
    t -= PR2;
    if (t < PR3) { g_hatt[t] = 0.f; return; }
    t -= PR3;
    if (t < PR4) { g_hcc[t] = 0.f; return; }
    t -= PR4;
    if (t < PR5) {
        int b = (int)(t / D_), c = (int)(t % D_);
        g_cc[t] = tok[(size_t)csi[b] * L_ * D_ + c];
    }
}

// ---------------- graph prep: counts -> scan -> scatter (CSR) ----------------
__global__ void count_kernel(const int* __restrict__ eidx, const int* __restrict__ etype) {
    int e = blockIdx.x * blockDim.x + threadIdx.x;
    if (e >= EE_) return;
    atomicAdd(&g_cnt[eidx[EE_ + e] * R_ + etype[e]], 1);
}
__global__ void scan_kernel() {
    __shared__ int part[1024];
    int tid = threadIdx.x;
    int base = tid * 40;
    int s = 0;
#pragma unroll 8
    for (int i = 0; i < 40; ++i) s += g_cnt[base + i];
    part[tid] = s;
    __syncthreads();
    for (int o = 1; o < 1024; o <<= 1) {
        int v = (tid >= o) ? part[tid - o] : 0;
        __syncthreads();
        part[tid] += v;
        __syncthreads();
    }
    int run = tid ? part[tid - 1] : 0;
#pragma unroll 8
    for (int i = 0; i < 40; ++i) {
        int c = g_cnt[base + i];
        g_off[base + i] = run;
        g_cur[base + i] = run;
        run += c;
    }
    if (tid == 1023) g_off[NR_] = run;
}
__global__ void scatter_kernel(const int* __restrict__ eidx, const int* __restrict__ etype) {
    int e = blockIdx.x * blockDim.x + threadIdx.x;
    if (e >= EE_) return;
    int pos = atomicAdd(&g_cur[eidx[EE_ + e] * R_ + etype[e]], 1);
    g_elist[pos] = eidx[e];
}

// grid (NN_, R_): one CTA per (dst, relation); 192 threads, 2 u32 each; 4-wide unroll.
__global__ void __launch_bounds__(192)
csr_agg_kernel(const uint32_t* __restrict__ xh) {
    int dst = blockIdx.x;
    int r   = blockIdx.y;
    int q = threadIdx.x * 2;
    int beg = g_off[dst * R_ + r];
    int end = g_off[dst * R_ + r + 1];
    float4 a = make_float4(0.f, 0.f, 0.f, 0.f);
    int i = beg;
    for (; i + 4 <= end; i += 4) {
        int s0 = g_elist[i], s1 = g_elist[i + 1], s2 = g_elist[i + 2], s3 = g_elist[i + 3];
        uint2 v0 = *(const uint2*)(xh + (size_t)s0 * D2_ + q);
        uint2 v1 = *(const uint2*)(xh + (size_t)s1 * D2_ + q);
        uint2 v2 = *(const uint2*)(xh + (size_t)s2 * D2_ + q);
        uint2 v3 = *(const uint2*)(xh + (size_t)s3 * D2_ + q);
        float2 f;
        f = unpackh2(v0.x); a.x += f.x; a.y += f.y;
        f = unpackh2(v0.y); a.z += f.x; a.w += f.y;
        f = unpackh2(v1.x); a.x += f.x; a.y += f.y;
        f = unpackh2(v1.y); a.z += f.x; a.w += f.y;
        f = unpackh2(v2.x); a.x += f.x; a.y += f.y;
        f = unpackh2(v2.y); a.z += f.x; a.w += f.y;
        f = unpackh2(v3.x); a.x += f.x; a.y += f.y;
        f = unpackh2(v3.y); a.z += f.x; a.w += f.y;
    }
    for (; i < end; ++i) {
        int src = g_elist[i];
        uint2 v = *(const uint2*)(xh + (size_t)src * D2_ + q);
        float2 f0 = unpackh2(v.x);
        float2 f1 = unpackh2(v.y);
        a.x += f0.x; a.y += f0.y; a.z += f1.x; a.w += f1.y;
    }
    float s = (end > beg) ? (1.f / (float)(end - beg)) : 0.f;
    size_t o = ((size_t)r * NN_ + dst) * D2_ + q;
    *(uint2*)&g_hh[o] = make_uint2(packh2(a.x * s, a.y * s), packh2(a.z * s, a.w * s));
}

// ---------------- fp16 single-pass tensor GEMM: 128x128 tile, occupancy 2 ----------------
// relu( [h0|h1|h2|h3|x] @ Wcat + bias ) -> fp16 Yh, or pooled mean|max -> Ev
#define GBM 128
#define GBN 128
#define GBK 32
#define NSTG (KTOT_ / GBK)   // 120
#define AP_  20              // A pitch u32 (16 k-pairs + 4 pad)
#define BP_  136             // B pitch u32 (128 + 8 pad) -> (8tc+g)%32 distinct
#define ASZ_ (GBM * AP_)     // 2560 u32
#define BSZ_ (16 * BP_)      // 2176 u32
#define SBUF (ASZ_ + BSZ_)   // 4736 u32 per stage (18944 B)
#define GSMEM (4 * SBUF * 4) // 75776 bytes -> 2 CTAs/SM

__global__ void __launch_bounds__(256, 2)
gemm_rgcn(const uint32_t* __restrict__ Hh, const uint32_t* __restrict__ Xh,
          const uint32_t* __restrict__ Bh,
          const float* __restrict__ bias,
          uint32_t* __restrict__ Yh, float* __restrict__ Ev) {
    extern __shared__ uint32_t sm[];
    const uint32_t sb = smem_u32(sm);
    const int tid  = threadIdx.x;
    const int wid  = tid >> 5;
    const int lane = tid & 31;
    const int g    = lane >> 2;
    const int tc   = lane & 3;
    const int wm   = wid & 3;        // 0..3 -> 32-row slice (one sequence)
    const int wn   = wid >> 2;       // 0..1 -> 64-col slice
    const int m0   = blockIdx.y * GBM;
    const int n0   = blockIdx.x * GBN;

    float acc[2][8][4];
#pragma unroll
    for (int i = 0; i < 2; ++i)
#pragma unroll
        for (int j = 0; j < 8; ++j)
#pragma unroll
            for (int q = 0; q < 4; ++q) acc[i][j][q] = 0.f;

    auto issueA = [&](int kc, int buf) {
        const int k0 = kc * GBK;
        const int r  = k0 / D_;
        const int dq = (k0 - r * D_) >> 1;
        const uint32_t* src = (r < 4) ? (Hh + ((size_t)r * NN_ + m0) * D2_ + dq)
                                      : (Xh + (size_t)m0 * D2_ + dq);
        const uint32_t aB = sb + (uint32_t)buf * (SBUF * 4);
#pragma unroll
        for (int i = 0; i < 2; ++i) {
            int c = tid + i * 256;
            int row = c >> 2, seg = c & 3;
            cp16(aB + row * (AP_ * 4) + seg * 16, src + (size_t)row * D2_ + seg * 4);
        }
    };
    auto issueB = [&](int kc, int buf) {
        const int kp0 = kc * 16;
        const uint32_t bbH = sb + (uint32_t)buf * (SBUF * 4) + ASZ_ * 4;
#pragma unroll
        for (int i = 0; i < 2; ++i) {
            int c = tid + i * 256;
            int row = c >> 5, seg = c & 31;
            size_t gidx = (size_t)(kp0 + row) * D_ + n0 + seg * 4;
            cp16(bbH + row * (BP_ * 4) + seg * 16, Bh + gidx);
        }
    };
    auto compute = [&](const uint32_t* s) {
        const uint32_t* AsH = s;
        const uint32_t* BsH = s + ASZ_;
#pragma unroll
        for (int ks = 0; ks < 2; ++ks) {
            const int kb = ks * 8;
            uint32_t aH[2][4];
#pragma unroll
            for (int mt = 0; mt < 2; ++mt) {
                int i0 = (wm * 32 + mt * 16 + g) * AP_ + kb + tc;
                int i1 = i0 + 8 * AP_;
                aH[mt][0] = AsH[i0]; aH[mt][1] = AsH[i1];
                aH[mt][2] = AsH[i0 + 4]; aH[mt][3] = AsH[i1 + 4];
            }
#pragma unroll
            for (int ng = 0; ng < 2; ++ng) {
                uint32_t bh[4][2];
#pragma unroll
                for (int q = 0; q < 4; ++q) {
                    int cb = wn * 64 + (ng * 4 + q) * 8;
                    int j0 = (kb + tc) * BP_ + cb + g;
                    int j1 = j0 + 4 * BP_;
                    bh[q][0] = BsH[j0]; bh[q][1] = BsH[j1];
                }
#pragma unroll
                for (int mt = 0; mt < 2; ++mt)
#pragma unroll
                    for (int q = 0; q < 4; ++q)
                        mma16816h(acc[mt][ng * 4 + q], aH[mt], bh[q]);
            }
        }
    };

    issueA(0, 0); issueB(0, 0);
    asm volatile("cp.async.commit_group;" ::: "memory");
    issueA(1, 1); issueB(1, 1);
    asm volatile("cp.async.commit_group;" ::: "memory");

#pragma unroll 1
    for (int kc = 0; kc < NSTG; ++kc) {
        if (kc + 2 < NSTG) {
            int buf = (kc + 2) & 3;
            issueA(kc + 2, buf);
            issueB(kc + 2, buf);
            asm volatile("cp.async.commit_group;" ::: "memory");
            asm volatile("cp.async.wait_group 2;" ::: "memory");
        } else if (kc + 1 < NSTG) {
            asm volatile("cp.async.wait_group 1;" ::: "memory");
        } else {
            asm volatile("cp.async.wait_group 0;" ::: "memory");
        }
        __syncthreads();
        compute(sm + (uint32_t)(kc & 3) * SBUF);
    }

    if (Ev) {
        // ---- pooled epilogue: bias+relu, mean/max over the 32 words (this warp's rows) ----
        const int seq = blockIdx.y * 4 + wm;
#pragma unroll
        for (int nt = 0; nt < 8; ++nt) {
            int col = n0 + wn * 64 + nt * 8 + tc * 2;
            float b0 = __ldg(bias + col);
            float b1 = __ldg(bias + col + 1);
            float s0 = 0.f, s1 = 0.f, x0 = 0.f, x1 = 0.f;
#pragma unroll
            for (int mt = 0; mt < 2; ++mt) {
                float v;
                v = fmaxf(acc[mt][nt][0] + b0, 0.f); s0 += v; x0 = fmaxf(x0, v);
                v = fmaxf(acc[mt][nt][2] + b0, 0.f); s0 += v; x0 = fmaxf(x0, v);
                v = fmaxf(acc[mt][nt][1] + b1, 0.f); s1 += v; x1 = fmaxf(x1, v);
                v = fmaxf(acc[mt][nt][3] + b1, 0.f); s1 += v; x1 = fmaxf(x1, v);
            }
#pragma unroll
            for (int off = 4; off <= 16; off <<= 1) {
                s0 += __shfl_xor_sync(0xffffffffu, s0, off);
                s1 += __shfl_xor_sync(0xffffffffu, s1, off);
                x0 = fmaxf(x0, __shfl_xor_sync(0xffffffffu, x0, off));
                x1 = fmaxf(x1, __shfl_xor_sync(0xffffffffu, x1, off));
            }
            if (lane < 4) {
                float* evr = Ev + (size_t)seq * (2 * DOUT_);
                evr[col]             = s0 * (1.f / WORDS_);
                evr[col + 1]         = s1 * (1.f / WORDS_);
                evr[DOUT_ + col]     = x0;
                evr[DOUT_ + col + 1] = x1;
            }
        }
    } else {
        // ---- standard epilogue: bias + relu -> fp16 ----
#pragma unroll
        for (int mt = 0; mt < 2; ++mt) {
            int row = m0 + wm * 32 + mt * 16 + g;
#pragma unroll
            for (int nt = 0; nt < 8; ++nt) {
                int col = n0 + wn * 64 + nt * 8 + tc * 2;
                float b0 = __ldg(bias + col);
                float b1 = __ldg(bias + col + 1);
                float2 v0 = make_float2(fmaxf(acc[mt][nt][0] + b0, 0.f),
                                        fmaxf(acc[mt][nt][1] + b1, 0.f));
                float2 v1 = make_float2(fmaxf(acc[mt][nt][2] + b0, 0.f),
                                        fmaxf(acc[mt][nt][3] + b1, 0.f));
                Yh[(size_t)row * D2_ + (col >> 1)]       = packh2(v0.x, v0.y);
                Yh[(size_t)(row + 8) * D2_ + (col >> 1)] = packh2(v1.x, v1.y);
            }
        }
    }
}

// ---------------- split-K fp32 GEMM for head ops ----------------
#define HB 64
#define HK 16
__global__ void __launch_bounds__(256)
sgemm_splitk(const float* __restrict__ A, const float* __restrict__ Bm,
             float* __restrict__ C, int M, int N, int K, int kchunk) {
    __shared__ float As[HK][HB + 4];
    __shared__ float Bs[HK][HB + 4];
    const int tid = threadIdx.x;
    const int tr = tid >> 4;
    const int tcol = tid & 15;
    const int m0 = blockIdx.y * HB;
    const int n0 = blockIdx.x * HB;
    const int k0 = blockIdx.z * kchunk;
    const int ar = tid >> 2, ac = (tid & 3) * 4;
    const int br = tid >> 4, bc = (tid & 15) * 4;
    float acc[4][4] = {};
    for (int kk = 0; kk < kchunk; kk += HK) {
        int k = k0 + kk;
        float4 av = (m0 + ar < M) ? *(const float4*)(A + (size_t)(m0 + ar) * K + k + ac)
                                  : make_float4(0.f, 0.f, 0.f, 0.f);
        As[ac + 0][ar] = av.x;
        As[ac + 1][ar] = av.y;
        As[ac + 2][ar] = av.z;
        As[ac + 3][ar] = av.w;
        *(float4*)&Bs[br][bc] = *(const float4*)(Bm + (size_t)(k + br) * N + n0 + bc);
        __syncthreads();
#pragma unroll
        for (int kq = 0; kq < HK; ++kq) {
            float rm[4], rn[4];
#pragma unroll
            for (int i = 0; i < 4; ++i) rm[i] = As[kq][tr * 4 + i];
#pragma unroll
            for (int j = 0; j < 4; ++j) rn[j] = Bs[kq][tcol * 4 + j];
#pragma unroll
            for (int i = 0; i < 4; ++i)
#pragma unroll
                for (int j = 0; j < 4; ++j)
                    acc[i][j] += rm[i] * rn[j];
        }
        __syncthreads();
    }
#pragma unroll
    for (int i = 0; i < 4; ++i) {
        int row = m0 + tr * 4 + i;
        if (row < M)
            red4(C + (size_t)row * N + n0 + tcol * 4,
                 acc[i][0], acc[i][1], acc[i][2], acc[i][3]);
    }
}

// ---------------- fused head kernels ----------------
__global__ void dotp_softmax_kernel(const float* __restrict__ att_w1, float* __restrict__ out) {
    int b = blockIdx.x;
    int tid = threadIdx.x;
    __shared__ float red[8];
    __shared__ float pv[EVI_];
#pragma unroll
    for (int e = 0; e < EVI_; ++e) {
        int s = b * EVI_ + e;
        float acc = 0.f;
        for (int k = tid; k < DOUT_; k += 256) {
            float h = g_hcc[b * DOUT_ + k] + g_hatt[(size_t)s * DOUT_ + k];
            acc += fmaxf(h, 0.f) * att_w1[k];
        }
#pragma unroll
        for (int o = 16; o; o >>= 1) acc += __shfl_down_sync(0xffffffffu, acc, o);
        if ((tid & 31) == 0) red[tid >> 5] = acc;
        __syncthreads();
        if (tid == 0) {
            float r = 0.f;
#pragma unroll
            for (int w = 0; w < 8; ++w) r += red[w];
            pv[e] = r;
        }
        __syncthreads();
    }
    if (tid == 0) {
        float m = -1e30f;
#pragma unroll
        for (int e = 0; e < EVI_; ++e) m = fmaxf(m, pv[e]);
        float s = 0.f;
        float ex[EVI_];
#pragma unroll
        for (int e = 0; e < EVI_; ++e) { ex[e] = expf(pv[e] - m); s += ex[e]; }
        float is = 1.f / s;
#pragma unroll
        for (int e = 0; e < EVI_; ++e) {
            g_a[b * EVI_ + e] = ex[e] * is;
            out[B_ * NC_ + b * EVI_ + e] = 1.f / (1.f + expf(-pv[e]));
        }
    }
}
__global__ void rep_bias_kernel(const float* __restrict__ concat_cls, const float* __restrict__ lin1_b) {
    int t = blockIdx.x * blockDim.x + threadIdx.x;
    const int W = 2 * DOUT_ + D_;
    const int NR = B_ * W;
    if (t < NR) {
        int b = t / W, c = t % W;
        if (c < 2 * DOUT_) {
            float acc = 0.f;
#pragma unroll
            for (int e = 0; e < EVI_; ++e)
                acc += g_a[b * EVI_ + e] * g_ev[(size_t)(b * EVI_ + e) * (2 * DOUT_) + c];
            g_rep[t] = acc;
        } else {
            g_rep[t] = concat_cls[b * D_ + (c - 2 * DOUT_)];
        }
    } else {
        int u = t - NR;
        if (u < B_ * LH_) g_hid[u] = lin1_b[u % LH_];
    }
}
__global__ void final_kernel(const float* __restrict__ lin2_w,
                             const float* __restrict__ lin2_b,
                             float* __restrict__ out) {
    int b = blockIdx.x;
    int tid = threadIdx.x;
    float a0 = 0.f, a1 = 0.f, a2 = 0.f;
    for (int k = tid; k < LH_; k += 128) {
        float h = fmaxf(g_hid[(size_t)b * LH_ + k], 0.f);
        a0 += h * lin2_w[k * NC_ + 0];
        a1 += h * lin2_w[k * NC_ + 1];
        a2 += h * lin2_w[k * NC_ + 2];
    }
#pragma unroll
    for (int o = 16; o; o >>= 1) {
        a0 += __shfl_down_sync(0xffffffffu, a0, o);
        a1 += __shfl_down_sync(0xffffffffu, a1, o);
        a2 += __shfl_down_sync(0xffffffffu, a2, o);
    }
    __shared__ float s0[4], s1[4], s2[4];
    if ((tid & 31) == 0) { int w = tid >> 5; s0[w] = a0; s1[w] = a1; s2[w] = a2; }
    __syncthreads();
    if (tid == 0) {
        float l0 = s0[0] + s0[1] + s0[2] + s0[3] + lin2_b[0];
        float l1 = s1[0] + s1[1] + s1[2] + s1[3] + lin2_b[1];
        float l2 = s2[0] + s2[1] + s2[2] + s2[3] + lin2_b[2];
        float m = fmaxf(l0, fmaxf(l1, l2));
        float lse = logf(expf(l0 - m) + expf(l1 - m) + expf(l2 - m)) + m;
        out[b * NC_ + 0] = l0 - lse;
        out[b * NC_ + 1] = l1 - lse;
        out[b * NC_ + 2] = l2 - lse;
    }
}

// ---------------- launch ----------------
extern "C" void kernel_launch(void* const* d_in, const int* in_sizes, int n_in,
                              void* d_out, int out_size) {
    const float* token_feats = (const float*)d_in[0];
    const float* concat_cls  = (const float*)d_in[1];
    const float* W_rel1      = (const float*)d_in[2];
    const float* W_root1     = (const float*)d_in[3];
    const float* b1          = (const float*)d_in[4];
    const float* W_rel2      = (const float*)d_in[5];
    const float* W_root2     = (const float*)d_in[6];
    const float* b2          = (const float*)d_in[7];
    const float* att_w0      = (const float*)d_in[8];
    const float* att_w1      = (const float*)d_in[9];
    const float* lin1_w      = (const float*)d_in[10];
    const float* lin1_b      = (const float*)d_in[11];
    const float* lin2_w      = (const float*)d_in[12];
    const float* lin2_b      = (const float*)d_in[13];
    const int*   wti         = (const int*)d_in[14];
    const int*   eidx        = (const int*)d_in[15];
    const int*   etype       = (const int*)d_in[16];
    const int*   csi         = (const int*)d_in[17];
    float* out = (float*)d_out;

    float *p_ev, *p_cc, *p_hcc, *p_hatt, *p_rep, *p_hid;
    uint32_t *p_hh, *p_xh, *p_yh, *p_bh1, *p_bh2;
    cudaGetSymbolAddress((void**)&p_ev,    g_ev);
    cudaGetSymbolAddress((void**)&p_cc,    g_cc);
    cudaGetSymbolAddress((void**)&p_hcc,   g_hcc);
    cudaGetSymbolAddress((void**)&p_hatt,  g_hatt);
    cudaGetSymbolAddress((void**)&p_rep,   g_rep);
    cudaGetSymbolAddress((void**)&p_hid,   g_hid);
    cudaGetSymbolAddress((void**)&p_hh,    g_hh);
    cudaGetSymbolAddress((void**)&p_xh,    g_xh);
    cudaGetSymbolAddress((void**)&p_yh,    g_yh);
    cudaGetSymbolAddress((void**)&p_bh1,   g_bh1);
    cudaGetSymbolAddress((void**)&p_bh2,   g_bh2);

    cudaFuncSetAttribute(gemm_rgcn, cudaFuncAttributeMaxDynamicSharedMemorySize, GSMEM);

    const int T = 256;
    const dim3 ggrid(D_ / GBN, NN_ / GBM);   // (6, 80) = 480 CTAs, 2/SM
    const dim3 agrid(NN_, R_);
    const int HKW = D_ + 2 * DOUT_;          // 2304

    // --- mega prep: zero cnt | x0 fp16 | both W fp16 | zero hatt/hcc | gather cc ---
    prep_kernel<<<(unsigned)((PRTOT + T - 1) / T), T>>>(token_feats, wti,
                                                        W_rel1, W_root1, W_rel2, W_root2, csi);

    // --- CSR build ---
    count_kernel<<<(EE_ + T - 1) / T, T>>>(eidx, etype);
    scan_kernel<<<1, 1024>>>();
    scatter_kernel<<<(EE_ + T - 1) / T, T>>>(eidx, etype);

    // --- hcc = cc @ W_top ---
    {
        dim3 hg(DOUT_ / HB, 1, 4);            // (12, 1, 4), kchunk=192
        sgemm_splitk<<<hg, 256>>>(p_cc, att_w0, p_hcc, B_, DOUT_, D_, D_ / 4);
    }

    // --- layer 1 (fp16 -> fp16) ---
    csr_agg_kernel<<<agrid, 192>>>(p_xh);
    gemm_rgcn<<<ggrid, 256, GSMEM>>>(p_hh, p_xh, p_bh1, b1, p_yh, nullptr);

    // --- layer 2 (fp16 -> pooled ev directly) ---
    csr_agg_kernel<<<agrid, 192>>>(p_yh);
    gemm_rgcn<<<ggrid, 256, GSMEM>>>(p_hh, p_yh, p_bh2, b2, nullptr, p_ev);

    // --- attention head: hatt = ev @ W_bot ---
    {
        dim3 hg(DOUT_ / HB, (SEQS_ + HB - 1) / HB, 6);   // (12, 5, 6), kchunk=256
        sgemm_splitk<<<hg, 256>>>(p_ev, att_w0 + (size_t)D_ * DOUT_, p_hatt,
                                  SEQS_, DOUT_, 2 * DOUT_, 2 * DOUT_ / 6);
    }
    dotp_softmax_kernel<<<B_, 256>>>(att_w1, out);

    // --- graph readout + classifier ---
    {
        int tot = B_ * HKW + B_ * LH_;
        rep_bias_kernel<<<(tot + T - 1) / T, T>>>(concat_cls, lin1_b);
    }
    {
        dim3 hg(LH_ / HB, (B_ + HB - 1) / HB, 8);        // (16, 1, 8), kchunk=288
        sgemm_splitk<<<hg, 256>>>(p_rep, lin1_w, p_hid, B_, LH_, HKW, HKW / 8);
    }
    final_kernel<<<B_, 128>>>(lin2_w, lin2_b, out);
}